// round 7
// baseline (speedup 1.0000x reference)
#include <cuda_runtime.h>
#include <cuda_pipeline.h>
#include <math.h>

// Problem constants (fixed by setup_inputs)
#define B       32
#define HQ      32
#define HKV     8
#define G       4      // HQ / HKV
#define D       128
#define BS      16     // block_size
#define MAXB    256    // max_blocks
#define TILE    64     // tokens per tile
#define TPC     128    // tokens per CTA (2 tiles)
#define NSC     32     // max CTA-splits = 4096 / TPC
#define NWARP   2
#define NTHR    (NWARP * 32)
#define ROWF    132    // padded K-row stride in floats (528B) -> conflict-free LDS

#define QSCALE  (0.08838834764831845f * 1.4426950408889634f)  // SCALE * log2(e)
#define NEG_BIG (-1e30f)
#define FULLM   0xffffffffu

// Scratch: partial (unnormalized) outputs + log-domain stats per (b, hkv, split, g)
__device__ float g_part_acc[B * HKV * NSC * G * D];   // 16.8 MB
__device__ float g_part_m  [B * HKV * NSC * G];
__device__ float g_part_l  [B * HKV * NSC * G];

__device__ __forceinline__ float warp_allmax(float v) {
    v = fmaxf(v, __shfl_xor_sync(FULLM, v, 16));
    v = fmaxf(v, __shfl_xor_sync(FULLM, v, 8));
    v = fmaxf(v, __shfl_xor_sync(FULLM, v, 4));
    v = fmaxf(v, __shfl_xor_sync(FULLM, v, 2));
    v = fmaxf(v, __shfl_xor_sync(FULLM, v, 1));
    return v;
}
__device__ __forceinline__ float warp_allsum(float v) {
    v += __shfl_xor_sync(FULLM, v, 16);
    v += __shfl_xor_sync(FULLM, v, 8);
    v += __shfl_xor_sync(FULLM, v, 4);
    v += __shfl_xor_sync(FULLM, v, 2);
    v += __shfl_xor_sync(FULLM, v, 1);
    return v;
}

__global__ __launch_bounds__(NTHR)
void attn_split_kernel(const float* __restrict__ q,
                       const float* __restrict__ kc,
                       const float* __restrict__ vc,
                       const int*   __restrict__ seqlens,
                       const int*   __restrict__ btab)
{
    extern __shared__ float smem[];
    float* qs   = smem;                         // G*D = 512 floats (pre-scaled q)
    float* Ks   = qs + G * D;                   // TILE * ROWF = 8448 floats
    float* ps   = Ks + TILE * ROWF;             // NWARP*32*4 = 256 floats
    float* smm  = ps + NWARP * 32 * 4;          // NWARP*G
    float* sml  = smm + NWARP * G;              // NWARP*G
    float* sma  = sml + NWARP * G;              // NWARP*G*D = 1024 floats

    const int b  = blockIdx.x;
    const int h  = blockIdx.y;
    const int sp = blockIdx.z;

    const int L     = seqlens[b];
    const int start = sp * TPC;
    if (start >= L) return;
    const int end = min(start + TPC, L);

    const int tid  = threadIdx.x;
    const int lane = tid & 31;
    const int w    = tid >> 5;

    const int* bt  = btab + b * MAXB;
    const int  bi0 = (start >> 4) + w * 2;      // tile0 block idx for this warp

    // stage K rows [w*32, w*32+32) of a tile from two blocks
    auto stageK = [&](int blkA, int blkB) {
        const float* kb0 = kc + ((blkA * BS) * HKV + h) * D + lane * 4;
        const float* kb1 = kc + ((blkB * BS) * HKV + h) * D + lane * 4;
        float* d0 = Ks + (w * 32) * ROWF + lane * 4;
#pragma unroll
        for (int r = 0; r < 16; r++)
            __pipeline_memcpy_async(d0 + r * ROWF, kb0 + r * (HKV * D), 16);
        float* d1 = Ks + (w * 32 + 16) * ROWF + lane * 4;
#pragma unroll
        for (int r = 0; r < 16; r++)
            __pipeline_memcpy_async(d1 + r * ROWF, kb1 + r * (HKV * D), 16);
        __pipeline_commit();
    };

    // --- stage K tile 0 ---
    const int blkA0 = bt[bi0], blkB0 = bt[bi0 + 1];
    stageK(blkA0, blkB0);

    // --- stage q (pre-scaled) ---
    {
        const float4* qg = (const float4*)(q + (b * HQ + h * G) * D);
        float4* qd = (float4*)qs;
#pragma unroll
        for (int i = tid; i < G * D / 4; i += NTHR) {
            float4 v = qg[i];
            v.x *= QSCALE; v.y *= QSCALE; v.z *= QSCALE; v.w *= QSCALE;
            qd[i] = v;
        }
    }
    __syncthreads();                 // q visible to all warps

    float  M[G], l[G];
    float4 a0 = {0,0,0,0}, a1 = {0,0,0,0}, a2 = {0,0,0,0}, a3 = {0,0,0,0};
#pragma unroll
    for (int g = 0; g < G; g++) { M[g] = NEG_BIG; l[g] = 0.f; }

    const bool tile1any = (start + TILE) < end;   // CTA-uniform

    // process one tile: scores + online merge + PV. Assumes K already waited.
    auto doTile = [&](int tbase /*global token of tile row0*/,
                      int blkA, int blkB, bool issueNext) {
        const bool wvalid = (tbase + w * 32) < end;
        float pt[G];                 // per-lane scaled probs
        float Mt[G], lt[G];

        if (wvalid) {
            const int  myrow = w * 32 + lane;
            const bool valid = (tbase + myrow) < end;

            float s0 = 0.f, s1 = 0.f, s2 = 0.f, s3 = 0.f;
            const float4* krow = (const float4*)(Ks + myrow * ROWF);
            const float4* q4p  = (const float4*)qs;
#pragma unroll
            for (int c = 0; c < 32; c++) {
                const float4 k4 = krow[c];
                const float4 qa = q4p[c];
                const float4 qb = q4p[32 + c];
                const float4 qcc = q4p[64 + c];
                const float4 qd = q4p[96 + c];
                s0 += qa.x*k4.x + qa.y*k4.y + qa.z*k4.z + qa.w*k4.w;
                s1 += qb.x*k4.x + qb.y*k4.y + qb.z*k4.z + qb.w*k4.w;
                s2 += qcc.x*k4.x + qcc.y*k4.y + qcc.z*k4.z + qcc.w*k4.w;
                s3 += qd.x*k4.x + qd.y*k4.y + qd.z*k4.z + qd.w*k4.w;
            }
            if (!valid) { s0 = s1 = s2 = s3 = NEG_BIG; }

            Mt[0] = warp_allmax(s0); Mt[1] = warp_allmax(s1);
            Mt[2] = warp_allmax(s2); Mt[3] = warp_allmax(s3);

            float p0 = exp2f(s0 - Mt[0]);
            float p1 = exp2f(s1 - Mt[1]);
            float p2 = exp2f(s2 - Mt[2]);
            float p3 = exp2f(s3 - Mt[3]);

            lt[0] = warp_allsum(p0); lt[1] = warp_allsum(p1);
            lt[2] = warp_allsum(p2); lt[3] = warp_allsum(p3);

            // online merge into (M, l, acc): alpha rescales old, beta scales new
            float alpha[G], beta[G];
#pragma unroll
            for (int g = 0; g < G; g++) {
                const float Mn = fmaxf(M[g], Mt[g]);
                alpha[g] = exp2f(M[g] - Mn);   // 0 when M was NEG_BIG
                beta[g]  = exp2f(Mt[g] - Mn);
                l[g] = l[g] * alpha[g] + lt[g] * beta[g];
                M[g] = Mn;
            }
            a0.x*=alpha[0]; a0.y*=alpha[0]; a0.z*=alpha[0]; a0.w*=alpha[0];
            a1.x*=alpha[1]; a1.y*=alpha[1]; a1.z*=alpha[1]; a1.w*=alpha[1];
            a2.x*=alpha[2]; a2.y*=alpha[2]; a2.z*=alpha[2]; a2.w*=alpha[2];
            a3.x*=alpha[3]; a3.y*=alpha[3]; a3.z*=alpha[3]; a3.w*=alpha[3];

            ((float4*)ps)[w * 32 + lane] =
                make_float4(p0 * beta[0], p1 * beta[1], p2 * beta[2], p3 * beta[3]);
        }
        __syncwarp();

        // overlap: kick off next tile's K staging before the PV phase
        if (issueNext) {
            const int blkA1 = bt[bi0 + 4], blkB1 = bt[bi0 + 5];
            stageK(blkA1, blkB1);
        }

        if (wvalid) {
            const float* vb0 = vc + ((blkA * BS) * HKV + h) * D + lane * 4;
            const float* vb1 = vc + ((blkB * BS) * HKV + h) * D + lane * 4;
            const float4* pw = (const float4*)ps + w * 32;
#pragma unroll
            for (int t0 = 0; t0 < 32; t0 += 4) {
                float4 v[4];
#pragma unroll
                for (int j = 0; j < 4; j++) {
                    const int tt = t0 + j;
                    const float* vb = (tt < 16) ? (vb0 + tt * (HKV * D))
                                                : (vb1 + (tt - 16) * (HKV * D));
                    v[j] = *(const float4*)vb;
                }
#pragma unroll
                for (int j = 0; j < 4; j++) {
                    const float4 pp = pw[t0 + j];
                    a0.x += pp.x*v[j].x; a0.y += pp.x*v[j].y; a0.z += pp.x*v[j].z; a0.w += pp.x*v[j].w;
                    a1.x += pp.y*v[j].x; a1.y += pp.y*v[j].y; a1.z += pp.y*v[j].z; a1.w += pp.y*v[j].w;
                    a2.x += pp.z*v[j].x; a2.y += pp.z*v[j].y; a2.z += pp.z*v[j].z; a2.w += pp.z*v[j].w;
                    a3.x += pp.w*v[j].x; a3.y += pp.w*v[j].y; a3.z += pp.w*v[j].z; a3.w += pp.w*v[j].w;
                }
            }
        }
        __syncwarp();
    };

    // tile 0 (K already in flight)
    __pipeline_wait_prior(0);
    __syncwarp();
    doTile(start, blkA0, blkB0, tile1any);

    // tile 1
    if (tile1any) {
        __pipeline_wait_prior(0);
        __syncwarp();
        const int blkA1 = bt[bi0 + 4], blkB1 = bt[bi0 + 5];
        doTile(start + TILE, blkA1, blkB1, false);
    }

    // --- write warp partials to smem ---
    if (lane == 0) {
#pragma unroll
        for (int g = 0; g < G; g++) {
            smm[w * G + g] = M[g];
            sml[w * G + g] = l[g];
        }
    }
    ((float4*)(sma + (w * G + 0) * D))[lane] = a0;
    ((float4*)(sma + (w * G + 1) * D))[lane] = a1;
    ((float4*)(sma + (w * G + 2) * D))[lane] = a2;
    ((float4*)(sma + (w * G + 3) * D))[lane] = a3;
    __syncthreads();

    // --- merge 2 warps: warp w handles heads {2w, 2w+1} ---
#pragma unroll
    for (int k = 0; k < 2; k++) {
        const int gg = 2 * w + k;
        const float Ma = smm[0 * G + gg];
        const float Mb = smm[1 * G + gg];
        const float Mm = fmaxf(Ma, Mb);
        const float e0 = exp2f(Ma - Mm);
        const float e1 = exp2f(Mb - Mm);
        const float Ls = e0 * sml[0 * G + gg] + e1 * sml[1 * G + gg];

        const float4 x0 = ((const float4*)(sma + (0 * G + gg) * D))[lane];
        const float4 x1 = ((const float4*)(sma + (1 * G + gg) * D))[lane];
        float4 o;
        o.x = e0 * x0.x + e1 * x1.x;
        o.y = e0 * x0.y + e1 * x1.y;
        o.z = e0 * x0.z + e1 * x1.z;
        o.w = e0 * x0.w + e1 * x1.w;

        const int idx = ((b * HKV + h) * NSC + sp) * G + gg;
        if (lane == 0) {
            g_part_m[idx] = Mm;
            g_part_l[idx] = Ls;
        }
        ((float4*)(g_part_acc + idx * D))[lane] = o;
    }
}

// Combine: 512 threads = 4 split-lanes x 128 dims. Parallel over splits.
__global__ __launch_bounds__(512)
void attn_combine_kernel(const int* __restrict__ seqlens,
                         float* __restrict__ out)
{
    __shared__ float sM;
    __shared__ float sO[4][D];
    __shared__ float sL[4];

    const int bh = blockIdx.x;          // b * HQ + hq
    const int b  = bh / HQ;
    const int hq = bh % HQ;
    const int h  = hq / G;
    const int g  = hq % G;
    const int d  = threadIdx.x & (D - 1);
    const int s  = threadIdx.x >> 7;    // split lane 0..3
    const int lane = threadIdx.x & 31;

    const int L   = seqlens[b];
    const int nsp = min(NSC, (L + TPC - 1) / TPC);

    const int base = ((b * HKV + h) * NSC) * G + g;  // + sp*G per split

    // Phase 1: global max over splits (warp 0, one parallel round for nsp<=32)
    if (threadIdx.x < 32) {
        float m1 = (lane < nsp) ? g_part_m[base + lane * G] : NEG_BIG;
        float m = warp_allmax(m1);
        if (lane == 0) sM = m;
    }
    __syncthreads();
    const float M = sM;

    // Phase 2: each split-lane accumulates splits s, s+4, ... (2-deep MLP)
    float o0 = 0.f, o1 = 0.f, L0 = 0.f, L1 = 0.f;
    int sp = s;
    for (; sp + 4 < nsp; sp += 8) {
        const int i0 = base + sp * G;
        const int i1 = base + (sp + 4) * G;
        const float e0 = exp2f(g_part_m[i0] - M);
        const float e1 = exp2f(g_part_m[i1] - M);
        L0 += e0 * g_part_l[i0];
        L1 += e1 * g_part_l[i1];
        o0 += e0 * g_part_acc[i0 * D + d];
        o1 += e1 * g_part_acc[i1 * D + d];
    }
    if (sp < nsp) {
        const int i0 = base + sp * G;
        const float e0 = exp2f(g_part_m[i0] - M);
        L0 += e0 * g_part_l[i0];
        o0 += e0 * g_part_acc[i0 * D + d];
    }

    sO[s][d] = o0 + o1;
    if (d == 0) sL[s] = L0 + L1;
    __syncthreads();

    // Phase 3: reduce the 4 split-lanes, lane set s==0 writes out
    if (s == 0) {
        const float oT = sO[0][d] + sO[1][d] + sO[2][d] + sO[3][d];
        const float LT = sL[0] + sL[1] + sL[2] + sL[3];
        out[bh * D + d] = oT / LT;
    }
}

extern "C" void kernel_launch(void* const* d_in, const int* in_sizes, int n_in,
                              void* d_out, int out_size)
{
    const float* q   = (const float*)d_in[0];
    const float* kc  = (const float*)d_in[1];
    const float* vc  = (const float*)d_in[2];
    const int*   sl  = (const int*)  d_in[3];
    const int*   bt  = (const int*)  d_in[4];
    float*       out = (float*)d_out;

    const int smem_bytes = (G * D + TILE * ROWF + NWARP * 32 * 4 +
                            NWARP * G * 2 + NWARP * G * D) * sizeof(float);

    dim3 grid1(B, HKV, NSC);
    attn_split_kernel<<<grid1, NTHR, smem_bytes>>>(q, kc, vc, sl, bt);
    attn_combine_kernel<<<B * HQ, 512>>>(sl, out);
}